// round 10
// baseline (speedup 1.0000x reference)
#include <cuda_runtime.h>
#include <cstdint>

#define BSZ    4096
#define HEADS  4
#define HALF   256
#define NKEYS  512
#define KNN    32
#define VDIM   1024
#define INDIM  1024
#define QCOLS  2048      // HEADS * K_DIM = 4*512

#define NCHUNK 4
#define CHROWS (BSZ / NCHUNK)   // 1024 rows per chunk
#define QBLKS  ((QCOLS / 128) * (CHROWS / 128))   // 16*8 = 128 q blocks per chunk

// ---- scratch (device globals: allocation-free) ----
__device__ float g_q[(size_t)BSZ * QCOLS];               // 32 MB
__device__ float g_scores[(size_t)8 * BSZ * NKEYS];      // 64 MB : [hs][b][n]

// ============================================================================
// q-GEMM body: one 128x128 output tile of q = x @ Wq  (K=1024), R5 math.
// ============================================================================
__device__ __forceinline__ void q_gemm_body(const float* __restrict__ A,
                                            const float* __restrict__ B,
                                            int bx, int by, int row0) {
    const int N = QCOLS;
    const int K = INDIM;
    __shared__ float As[2][16][128];
    __shared__ float Bs[2][16][128];

    const int tid = threadIdx.x;
    const float* Ab = A + (size_t)(row0 + by * 128) * INDIM;
    const float* Bb = B + bx * 128;

    const int a_row0 = tid >> 2;                 // 0..63
    const int a_row1 = a_row0 + 64;
    const int a_kq   = (tid & 3) * 4;            // 0,4,8,12
    const int b_kr0  = tid >> 5;                 // 0..7
    const int b_kr1  = b_kr0 + 8;
    const int b_cq   = (tid & 31) * 4;           // 0..124

    float acc[8][8];
    #pragma unroll
    for (int i = 0; i < 8; i++)
        #pragma unroll
        for (int j = 0; j < 8; j++) acc[i][j] = 0.f;

    const int tx = (tid & 15) * 8;
    const int ty = (tid >> 4) * 8;

    float4 ra0, ra1, rb0, rb1;

    ra0 = *(const float4*)(Ab + (size_t)a_row0 * INDIM + a_kq);
    ra1 = *(const float4*)(Ab + (size_t)a_row1 * INDIM + a_kq);
    rb0 = *(const float4*)(Bb + (size_t)b_kr0 * N + b_cq);
    rb1 = *(const float4*)(Bb + (size_t)b_kr1 * N + b_cq);
    As[0][a_kq + 0][a_row0] = ra0.x; As[0][a_kq + 1][a_row0] = ra0.y;
    As[0][a_kq + 2][a_row0] = ra0.z; As[0][a_kq + 3][a_row0] = ra0.w;
    As[0][a_kq + 0][a_row1] = ra1.x; As[0][a_kq + 1][a_row1] = ra1.y;
    As[0][a_kq + 2][a_row1] = ra1.z; As[0][a_kq + 3][a_row1] = ra1.w;
    *(float4*)&Bs[0][b_kr0][b_cq] = rb0;
    *(float4*)&Bs[0][b_kr1][b_cq] = rb1;
    __syncthreads();

    const int ntiles = K / 16;
    for (int t = 0; t < ntiles; t++) {
        const int cur = t & 1;
        if (t + 1 < ntiles) {
            const int k0 = (t + 1) * 16;
            ra0 = *(const float4*)(Ab + (size_t)a_row0 * INDIM + k0 + a_kq);
            ra1 = *(const float4*)(Ab + (size_t)a_row1 * INDIM + k0 + a_kq);
            rb0 = *(const float4*)(Bb + (size_t)(k0 + b_kr0) * N + b_cq);
            rb1 = *(const float4*)(Bb + (size_t)(k0 + b_kr1) * N + b_cq);
        }

        #pragma unroll
        for (int kk = 0; kk < 16; kk++) {
            float a[8], b[8];
            *(float4*)(a)     = *(float4*)&As[cur][kk][ty];
            *(float4*)(a + 4) = *(float4*)&As[cur][kk][ty + 4];
            *(float4*)(b)     = *(float4*)&Bs[cur][kk][tx];
            *(float4*)(b + 4) = *(float4*)&Bs[cur][kk][tx + 4];
            #pragma unroll
            for (int i = 0; i < 8; i++)
                #pragma unroll
                for (int j = 0; j < 8; j++) acc[i][j] += a[i] * b[j];
        }

        if (t + 1 < ntiles) {
            const int nxt = cur ^ 1;
            As[nxt][a_kq + 0][a_row0] = ra0.x; As[nxt][a_kq + 1][a_row0] = ra0.y;
            As[nxt][a_kq + 2][a_row0] = ra0.z; As[nxt][a_kq + 3][a_row0] = ra0.w;
            As[nxt][a_kq + 0][a_row1] = ra1.x; As[nxt][a_kq + 1][a_row1] = ra1.y;
            As[nxt][a_kq + 2][a_row1] = ra1.z; As[nxt][a_kq + 3][a_row1] = ra1.w;
            *(float4*)&Bs[nxt][b_kr0][b_cq] = rb0;
            *(float4*)&Bs[nxt][b_kr1][b_cq] = rb1;
            __syncthreads();
        }
    }

    #pragma unroll
    for (int i = 0; i < 8; i++) {
        float* Cp = g_q + (size_t)(row0 + by * 128 + ty + i) * N + bx * 128 + tx;
        *(float4*)(Cp)     = make_float4(acc[i][0], acc[i][1], acc[i][2], acc[i][3]);
        *(float4*)(Cp + 4) = make_float4(acc[i][4], acc[i][5], acc[i][6], acc[i][7]);
    }
}

// ============================================================================
// topk+gather body: one batch row b. Warps 0-3: per-head top-k + softmax into
// smem; then all 256 threads gather & weighted-sum (same accumulation order
// as the proven split kernels).
// ============================================================================
__device__ __forceinline__ void tg_body(const float* __restrict__ values,
                                        float* __restrict__ out, int b) {
    const int tid  = threadIdx.x;
    const int wid  = tid >> 5;
    const int lane = tid & 31;

    __shared__ float sv[HEADS][2][KNN];
    __shared__ int   si[HEADS][2][KNN];
    __shared__ float sbest[HEADS][KNN];
    __shared__ int   sbf[HEADS][KNN];
    __shared__ float ws[HEADS * KNN];
    __shared__ int   is[HEADS * KNN];

    if (wid < 4) {
        const int h = wid;
        #pragma unroll
        for (int s = 0; s < 2; s++) {
            const float* p = g_scores + ((size_t)(h * 2 + s)) * BSZ * NKEYS + (size_t)b * NKEYS;
            float v[16];
            #pragma unroll
            for (int j = 0; j < 16; j++) v[j] = p[j * 32 + lane];

            for (int r = 0; r < KNN; r++) {
                float bv = -1e30f; int bi = 1 << 30;
                #pragma unroll
                for (int j = 0; j < 16; j++) {
                    if (v[j] > bv) { bv = v[j]; bi = j * 32 + lane; }
                }
                #pragma unroll
                for (int off = 16; off; off >>= 1) {
                    float ov = __shfl_xor_sync(0xffffffffu, bv, off);
                    int   oi = __shfl_xor_sync(0xffffffffu, bi, off);
                    if (ov > bv || (ov == bv && oi < bi)) { bv = ov; bi = oi; }
                }
                if ((bi & 31) == lane) {
                    int rem = bi >> 5;
                    #pragma unroll
                    for (int j = 0; j < 16; j++) if (j == rem) v[j] = -1e30f;
                }
                if (lane == 0) { sv[h][s][r] = bv; si[h][s][r] = bi; }
            }
        }
        __syncwarp();

        float cv[KNN];
        float s1l = sv[h][0][lane];
        #pragma unroll
        for (int j = 0; j < KNN; j++) cv[j] = s1l + sv[h][1][j];

        for (int r = 0; r < KNN; r++) {
            float bv = -1e30f; int bf = 1 << 30;
            #pragma unroll
            for (int j = 0; j < KNN; j++) {
                if (cv[j] > bv) { bv = cv[j]; bf = lane * 32 + j; }
            }
            #pragma unroll
            for (int off = 16; off; off >>= 1) {
                float ov = __shfl_xor_sync(0xffffffffu, bv, off);
                int   oi = __shfl_xor_sync(0xffffffffu, bf, off);
                if (ov > bv || (ov == bv && oi < bf)) { bv = ov; bf = oi; }
            }
            if ((bf >> 5) == lane) {
                int rem = bf & 31;
                #pragma unroll
                for (int j = 0; j < KNN; j++) if (j == rem) cv[j] = -1e30f;
            }
            if (lane == 0) { sbest[h][r] = bv; sbf[h][r] = bf; }
        }
        __syncwarp();

        float m = sbest[h][0];
        float e = expf(sbest[h][lane] - m);
        float sum = e;
        #pragma unroll
        for (int off = 16; off; off >>= 1) sum += __shfl_xor_sync(0xffffffffu, sum, off);
        float wgt = e / sum;

        int f = sbf[h][lane];
        int index = si[h][0][f >> 5] * NKEYS + si[h][1][f & 31];

        ws[h * KNN + lane] = wgt;
        is[h * KNN + lane] = index;
    }
    __syncthreads();

    const float4* V = (const float4*)values;
    float4 acc = make_float4(0.f, 0.f, 0.f, 0.f);

    #pragma unroll 8
    for (int k = 0; k < HEADS * KNN; k++) {
        float w = ws[k];
        size_t row = (size_t)is[k];
        float4 v = V[row * (VDIM / 4) + tid];
        acc.x += w * v.x; acc.y += w * v.y;
        acc.z += w * v.z; acc.w += w * v.w;
    }
    ((float4*)out)[(size_t)b * (VDIM / 4) + tid] = acc;
}

// ============================================================================
// Standalone kernels
// ============================================================================
__global__ void __launch_bounds__(256, 2) q_gemm_k(const float* __restrict__ A,
                                                   const float* __restrict__ B,
                                                   int row0) {
    q_gemm_body(A, B, blockIdx.x, blockIdx.y, row0);
}

__global__ void __launch_bounds__(256) tg_k(const float* __restrict__ values,
                                            float* __restrict__ out, int row0) {
    tg_body(values, out, row0 + blockIdx.x);
}

// Fused: blocks [0, QBLKS) run q_gemm(chunk qrow0); blocks [QBLKS, QBLKS+CHROWS)
// run topk+gather rows of chunk grow0. Block-level concurrency = overlap of the
// DRAM-bound gather with the FFMA-bound GEMM, no streams needed.
__global__ void __launch_bounds__(256, 2) fused_gq_k(const float* __restrict__ values,
                                                     float* __restrict__ out, int grow0,
                                                     const float* __restrict__ A,
                                                     const float* __restrict__ B,
                                                     int qrow0) {
    const int bid = blockIdx.x;
    if (bid < QBLKS) {
        q_gemm_body(A, B, bid & 15, bid >> 4, qrow0);
    } else {
        tg_body(values, out, grow0 + (bid - QBLKS));
    }
}

// ============================================================================
// score GEMM (per chunk & hs: M=1024, N=512, K=256), R5 math + row0
// ============================================================================
__global__ void __launch_bounds__(256, 2) score_gemm(const float* __restrict__ keys,
                                                     int row0) {
    const int hs = blockIdx.z;
    const float* Ab = g_q + hs * HALF + (size_t)(row0 + blockIdx.y * 128) * QCOLS;
    const float* Bb = keys + (size_t)hs * NKEYS * HALF + (size_t)blockIdx.x * 128 * HALF;
    float* Cb = g_scores + (size_t)hs * BSZ * NKEYS;

    __shared__ float As[2][16][128];
    __shared__ float Bs[2][16][128];

    const int tid = threadIdx.x;
    const int a_row0 = tid >> 2;
    const int a_row1 = a_row0 + 64;
    const int a_kq   = (tid & 3) * 4;

    float acc[8][8];
    #pragma unroll
    for (int i = 0; i < 8; i++)
        #pragma unroll
        for (int j = 0; j < 8; j++) acc[i][j] = 0.f;

    const int tx = (tid & 15) * 8;
    const int ty = (tid >> 4) * 8;

    float4 ra0, ra1, rb0, rb1;

    ra0 = *(const float4*)(Ab + (size_t)a_row0 * QCOLS + a_kq);
    ra1 = *(const float4*)(Ab + (size_t)a_row1 * QCOLS + a_kq);
    rb0 = *(const float4*)(Bb + (size_t)a_row0 * HALF + a_kq);
    rb1 = *(const float4*)(Bb + (size_t)a_row1 * HALF + a_kq);
    As[0][a_kq + 0][a_row0] = ra0.x; As[0][a_kq + 1][a_row0] = ra0.y;
    As[0][a_kq + 2][a_row0] = ra0.z; As[0][a_kq + 3][a_row0] = ra0.w;
    As[0][a_kq + 0][a_row1] = ra1.x; As[0][a_kq + 1][a_row1] = ra1.y;
    As[0][a_kq + 2][a_row1] = ra1.z; As[0][a_kq + 3][a_row1] = ra1.w;
    Bs[0][a_kq + 0][a_row0] = rb0.x; Bs[0][a_kq + 1][a_row0] = rb0.y;
    Bs[0][a_kq + 2][a_row0] = rb0.z; Bs[0][a_kq + 3][a_row0] = rb0.w;
    Bs[0][a_kq + 0][a_row1] = rb1.x; Bs[0][a_kq + 1][a_row1] = rb1.y;
    Bs[0][a_kq + 2][a_row1] = rb1.z; Bs[0][a_kq + 3][a_row1] = rb1.w;
    __syncthreads();

    const int ntiles = HALF / 16;
    for (int t = 0; t < ntiles; t++) {
        const int cur = t & 1;
        if (t + 1 < ntiles) {
            const int k0 = (t + 1) * 16;
            ra0 = *(const float4*)(Ab + (size_t)a_row0 * QCOLS + k0 + a_kq);
            ra1 = *(const float4*)(Ab + (size_t)a_row1 * QCOLS + k0 + a_kq);
            rb0 = *(const float4*)(Bb + (size_t)a_row0 * HALF + k0 + a_kq);
            rb1 = *(const float4*)(Bb + (size_t)a_row1 * HALF + k0 + a_kq);
        }

        #pragma unroll
        for (int kk = 0; kk < 16; kk++) {
            float a[8], b[8];
            *(float4*)(a)     = *(float4*)&As[cur][kk][ty];
            *(float4*)(a + 4) = *(float4*)&As[cur][kk][ty + 4];
            *(float4*)(b)     = *(float4*)&Bs[cur][kk][tx];
            *(float4*)(b + 4) = *(float4*)&Bs[cur][kk][tx + 4];
            #pragma unroll
            for (int i = 0; i < 8; i++)
                #pragma unroll
                for (int j = 0; j < 8; j++) acc[i][j] += a[i] * b[j];
        }

        if (t + 1 < ntiles) {
            const int nxt = cur ^ 1;
            As[nxt][a_kq + 0][a_row0] = ra0.x; As[nxt][a_kq + 1][a_row0] = ra0.y;
            As[nxt][a_kq + 2][a_row0] = ra0.z; As[nxt][a_kq + 3][a_row0] = ra0.w;
            As[nxt][a_kq + 0][a_row1] = ra1.x; As[nxt][a_kq + 1][a_row1] = ra1.y;
            As[nxt][a_kq + 2][a_row1] = ra1.z; As[nxt][a_kq + 3][a_row1] = ra1.w;
            Bs[nxt][a_kq + 0][a_row0] = rb0.x; Bs[nxt][a_kq + 1][a_row0] = rb0.y;
            Bs[nxt][a_kq + 2][a_row0] = rb0.z; Bs[nxt][a_kq + 3][a_row0] = rb0.w;
            Bs[nxt][a_kq + 0][a_row1] = rb1.x; Bs[nxt][a_kq + 1][a_row1] = rb1.y;
            Bs[nxt][a_kq + 2][a_row1] = rb1.z; Bs[nxt][a_kq + 3][a_row1] = rb1.w;
            __syncthreads();
        }
    }

    #pragma unroll
    for (int i = 0; i < 8; i++) {
        float* Cp = Cb + (size_t)(row0 + blockIdx.y * 128 + ty + i) * NKEYS + blockIdx.x * 128 + tx;
        *(float4*)(Cp)     = make_float4(acc[i][0], acc[i][1], acc[i][2], acc[i][3]);
        *(float4*)(Cp + 4) = make_float4(acc[i][4], acc[i][5], acc[i][6], acc[i][7]);
    }
}

// ============================================================================
// Launch: chunked software pipeline on the DEFAULT stream (no stream/event
// objects — allocation-free, graph-capturable):
//   Q0, S0, [G0 || Q1], S1, [G1 || Q2], S2, [G2 || Q3], S3, G3
// ============================================================================
extern "C" void kernel_launch(void* const* d_in, const int* in_sizes, int n_in,
                              void* d_out, int out_size) {
    const float* x      = (const float*)d_in[0];   // (4096, 1024)
    const float* wq     = (const float*)d_in[1];   // (1024, 2048)
    const float* keys   = (const float*)d_in[2];   // (4, 2, 512, 256)
    const float* values = (const float*)d_in[3];   // (262144, 1024)
    float* out = (float*)d_out;                    // (4096, 1024)

    dim3 sgrid(NKEYS / 128, CHROWS / 128, 8);      // (4, 8, 8)

    // chunk 0 query GEMM
    q_gemm_k<<<dim3(QCOLS / 128, CHROWS / 128), 256>>>(x, wq, 0);
    score_gemm<<<sgrid, 256>>>(keys, 0);

    for (int c = 0; c < NCHUNK - 1; c++) {
        // gather(c) overlapped with q_gemm(c+1) in one launch
        fused_gq_k<<<QBLKS + CHROWS, 256>>>(values, out, c * CHROWS,
                                            x, wq, (c + 1) * CHROWS);
        score_gemm<<<sgrid, 256>>>(keys, (c + 1) * CHROWS);
    }
    // final chunk topk+gather
    tg_k<<<CHROWS, 256>>>(values, out, (NCHUNK - 1) * CHROWS);
}